// round 6
// baseline (speedup 1.0000x reference)
#include <cuda_runtime.h>
#include <math.h>

#define BB 2
#define NN 512
#define DIN 512
#define DM 256
#define C2LOG2E 2.885390081777927f   // 2*log2(e)

// scratch (static device globals — no allocation). g_qt padded +8 rows so the
// score kernel's prefetch can run past the end unconditionally.
__device__ float g_h[BB * NN * DM];            // h[b][n][d] = tanh(x@Wx+bx)
__device__ float g_p[BB * NN * DM];            // P row-major: exp2(c*(u+bp))
__device__ float g_qt[BB * DM * NN + 8 * NN];  // Q transposed: exp2(-c*u)[b][d][n]

__device__ __forceinline__ float ex2_fast(float x) {
    float y; asm("ex2.approx.f32 %0, %1;" : "=f"(y) : "f"(x)); return y;
}
__device__ __forceinline__ float rcp_fast(float x) {
    float y; asm("rcp.approx.f32 %0, %1;" : "=f"(y) : "f"(x)); return y;
}

// ---------------------------------------------------------------------------
// Kernel A: h = tanh(x @ Wx + bx); P (row-major) / Q (transposed).
// 4 rows per block, K split across two thread-halves.
// grid = 256 blocks, 512 threads.
// ---------------------------------------------------------------------------
__global__ __launch_bounds__(512) void kA(const float* __restrict__ x,
                                          const float* __restrict__ pos,
                                          const float* __restrict__ Wx,
                                          const float* __restrict__ bx,
                                          const float* __restrict__ Wp,
                                          const float* __restrict__ bp) {
    __shared__ float s_x[DIN][4];    // 8KB, x tile transposed
    __shared__ float s_part[4][DM];  // 4KB, partial sums from upper K-half
    const int t = threadIdx.x;
    const int row0 = blockIdx.x * 4;
    const int c  = t & (DM - 1);     // output column d
    const int kh = t >> 8;           // K-half: 0 or 1

    for (int e = t; e < DIN * 4; e += 512) {
        int r = e >> 9, cc = e & (DIN - 1);
        s_x[cc][r] = x[(row0 + r) * DIN + cc];   // coalesced
    }
    __syncthreads();

    float a0 = 0.f, a1 = 0.f, a2 = 0.f, a3 = 0.f;
    const int kb = kh << 8;
#pragma unroll 8
    for (int k = 0; k < 256; k++) {
        float wv = Wx[(kb + k) * DM + c];            // coalesced, L2-hot
        float4 xv = *(const float4*)&s_x[kb + k][0]; // broadcast LDS.128
        a0 += xv.x * wv; a1 += xv.y * wv;
        a2 += xv.z * wv; a3 += xv.w * wv;
    }
    if (kh) {
        s_part[0][c] = a0; s_part[1][c] = a1;
        s_part[2][c] = a2; s_part[3][c] = a3;
    }
    __syncthreads();
    if (!kh) {
        const float bias = bx[c];
        a0 += s_part[0][c] + bias;
        a1 += s_part[1][c] + bias;
        a2 += s_part[2][c] + bias;
        a3 += s_part[3][c] + bias;
        g_h[(row0 + 0) * DM + c] = tanhf(a0);
        g_h[(row0 + 1) * DM + c] = tanhf(a1);
        g_h[(row0 + 2) * DM + c] = tanhf(a2);
        g_h[(row0 + 3) * DM + c] = tanhf(a3);

        const int b = row0 / NN;
        const int n0 = row0 % NN;
        const float w0 = Wp[0 * DM + c], w1 = Wp[1 * DM + c];
        const float w2 = Wp[2 * DM + c], w3 = Wp[3 * DM + c];
        const float bpv = bp[c];
#pragma unroll
        for (int r = 0; r < 4; r++) {
            const float* p = pos + (row0 + r) * 4;
            float u = p[0] * w0 + p[1] * w1 + p[2] * w2 + p[3] * w3;
            g_p[(row0 + r) * DM + c] = ex2_fast(C2LOG2E * (u + bpv));
            g_qt[(b * DM + c) * NN + n0 + r] = ex2_fast(-C2LOG2E * u);
        }
    }
}

// ---------------------------------------------------------------------------
// Kernel Score: raw scores -> attn_out.  Block = 2 query rows x 256 j's.
// grid = (B*N/2)*2 = 1024 blocks, 256 threads. Thread owns one j.
// score_ij = W - 2*sum_d w_d / (1 + P_i[d]*Q_j[d])
// Branch-free 8-deep prefetch; wn-multiplies overlap the rcp latency.
// ---------------------------------------------------------------------------
__global__ __launch_bounds__(256) void kScore(const float* __restrict__ w,
                                              float* __restrict__ attn_out) {
    __shared__ float s_pi[DM][2];   // P rows i0, i0+1 : 2KB
    __shared__ float s_wn[DM];      // -2*w : 1KB
    __shared__ float s_W;

    const int t = threadIdx.x;
    const int jt = blockIdx.x & 1;            // j-tile
    const int it = blockIdx.x >> 1;           // row-pair index
    const int b  = it / (NN / 2);
    const int i0 = (it % (NN / 2)) * 2;
    const int j  = jt * 256 + t;

    if (t < DM) s_wn[t] = -2.0f * w[t];
    if (t < 32) {
        float s = 0.f;
#pragma unroll
        for (int k = 0; k < 8; k++) s += w[t + 32 * k];
#pragma unroll
        for (int o = 16; o; o >>= 1) s += __shfl_xor_sync(0xffffffffu, s, o);
        if (t == 0) s_W = s;
    }
    {
        const float* prow = g_p + (b * NN + i0) * DM;
        for (int e = t; e < 2 * DM; e += 256) {
            int r = e >> 8, d = e & (DM - 1);
            s_pi[d][r] = prow[r * DM + d];
        }
    }
    __syncthreads();
    const float W = s_W;

    float a0 = 0.f, a1 = 0.f;
    const float* qp = g_qt + b * DM * NN + j;
    float qbuf[8];
#pragma unroll
    for (int p = 0; p < 8; p++) qbuf[p] = qp[p * NN];

#pragma unroll 2
    for (int d0 = 0; d0 < DM; d0 += 8) {
        float qc[8];
#pragma unroll
        for (int p = 0; p < 8; p++) qc[p] = qbuf[p];
#pragma unroll
        for (int p = 0; p < 8; p++) qbuf[p] = qp[(d0 + 8 + p) * NN];  // padded, branch-free
#pragma unroll
        for (int dd = 0; dd < 8; dd++) {
            const int d = d0 + dd;
            const float2 pi = *(const float2*)&s_pi[d][0];  // broadcast LDS.64
            const float wn = s_wn[d];
            const float qj = qc[dd];
            float de0 = fmaf(pi.x, qj, 1.0f);
            float de1 = fmaf(pi.y, qj, 1.0f);
            float prod = de0 * de1;
            float n0 = wn * de1;          // overlap MUFU latency
            float n1 = wn * de0;
            float r = rcp_fast(prod);
            a0 += n0 * r;
            a1 += n1 * r;
        }
    }
    float* arow = attn_out + (b * NN + i0) * NN + j;
    arow[0]  = W + a0;
    arow[NN] = W + a1;
}

// ---------------------------------------------------------------------------
// Kernel SoftOut: masked softmax over 4 rows + output GEMM.
// grid = B*N/4 = 256 blocks, 512 threads.
// ---------------------------------------------------------------------------
__global__ __launch_bounds__(512) void kSoftOut(const int* __restrict__ mask,
                                                float* __restrict__ out,
                                                float* __restrict__ attn_out) {
    __shared__ float s_attn[4][NN];   // scores -> probs, 8KB

    const int t = threadIdx.x;
    const int blk = blockIdx.x;
    const int b = blk / (NN / 4);
    const int i0 = (blk % (NN / 4)) * 4;

    {
        const float4* src = (const float4*)(attn_out + (b * NN + i0) * NN);
        float4* dst = (float4*)&s_attn[0][0];
        for (int e = t; e < 4 * NN / 4; e += 512) dst[e] = src[e];
    }
    __syncthreads();

    const int wid = t >> 5, lane = t & 31;
    if (wid < 4) {
        const int i = i0 + wid;
        const int4* m4 = (const int4*)(mask + (b * NN + i) * NN);
        float4* s4 = (float4*)&s_attn[wid][0];
        int4 mv[4];
        float4 sv[4];
#pragma unroll
        for (int k = 0; k < 4; k++) {
            mv[k] = m4[lane + 32 * k];
            sv[k] = s4[lane + 32 * k];
        }
        float mx = -INFINITY;
#pragma unroll
        for (int k = 0; k < 4; k++) {
            if (mv[k].x) mx = fmaxf(mx, sv[k].x);
            if (mv[k].y) mx = fmaxf(mx, sv[k].y);
            if (mv[k].z) mx = fmaxf(mx, sv[k].z);
            if (mv[k].w) mx = fmaxf(mx, sv[k].w);
        }
#pragma unroll
        for (int o = 16; o; o >>= 1) mx = fmaxf(mx, __shfl_xor_sync(0xffffffffu, mx, o));
        float sum = 0.f;
#pragma unroll
        for (int k = 0; k < 4; k++) {
            sv[k].x = mv[k].x ? __expf(sv[k].x - mx) : 0.f;
            sv[k].y = mv[k].y ? __expf(sv[k].y - mx) : 0.f;
            sv[k].z = mv[k].z ? __expf(sv[k].z - mx) : 0.f;
            sv[k].w = mv[k].w ? __expf(sv[k].w - mx) : 0.f;
            sum += sv[k].x + sv[k].y + sv[k].z + sv[k].w;
        }
#pragma unroll
        for (int o = 16; o; o >>= 1) sum += __shfl_xor_sync(0xffffffffu, sum, o);
        const float inv = (sum > 0.f) ? 1.f / sum : 0.f;
        float4* arow4 = (float4*)(attn_out + (b * NN + i) * NN);
#pragma unroll
        for (int k = 0; k < 4; k++) {
            sv[k].x *= inv; sv[k].y *= inv; sv[k].z *= inv; sv[k].w *= inv;
            s4[lane + 32 * k] = sv[k];
            arow4[lane + 32 * k] = sv[k];
        }
    }
    __syncthreads();

    // output: thread t -> d = t&255, rows {2*half, 2*half+1}
    const int d = t & (DM - 1);
    const int half = t >> 8;
    float o0 = 0.f, o1 = 0.f;
    const float* hb = g_h + b * NN * DM + d;
    const float4* pA = (const float4*)&s_attn[2 * half][0];
    const float4* pB = (const float4*)&s_attn[2 * half + 1][0];
#pragma unroll 2
    for (int j4 = 0; j4 < NN / 4; j4++) {
        float4 a = pA[j4];  // broadcast LDS.128
        float4 c = pB[j4];
        float h0 = hb[(4 * j4 + 0) * DM];
        float h1 = hb[(4 * j4 + 1) * DM];
        float h2 = hb[(4 * j4 + 2) * DM];
        float h3 = hb[(4 * j4 + 3) * DM];
        o0 += a.x * h0 + a.y * h1 + a.z * h2 + a.w * h3;
        o1 += c.x * h0 + c.y * h1 + c.z * h2 + c.w * h3;
    }
    out[(b * NN + i0 + 2 * half + 0) * DM + d] = o0;
    out[(b * NN + i0 + 2 * half + 1) * DM + d] = o1;
}

// ---------------------------------------------------------------------------
extern "C" void kernel_launch(void* const* d_in, const int* in_sizes, int n_in,
                              void* d_out, int out_size) {
    const float* x    = (const float*)d_in[0];  // [2,512,512]
    const float* pos  = (const float*)d_in[1];  // [2,512,4]
    const int*   mask = (const int*)  d_in[2];  // [2,512,512]
    const float* Wx   = (const float*)d_in[3];  // [512,256]
    const float* bx   = (const float*)d_in[4];  // [256]
    const float* Wp   = (const float*)d_in[5];  // [4,256]
    const float* bp   = (const float*)d_in[6];  // [256]
    const float* w    = (const float*)d_in[7];  // [256]

    float* out      = (float*)d_out;            // [2,512,256]
    float* attn_out = out + BB * NN * DM;       // [2,512,512]

    kA<<<BB * NN / 4, 512>>>(x, pos, Wx, bx, Wp, bp);
    kScore<<<BB * NN, 256>>>(w, attn_out);
    kSoftOut<<<BB * NN / 4, 512>>>(mask, out, attn_out);
}

// round 7
// speedup vs baseline: 1.4338x; 1.4338x over previous
#include <cuda_runtime.h>
#include <math.h>

#define BB 2
#define NN 512
#define DIN 512
#define DM 256
#define C2LOG2E 2.885390081777927f   // 2*log2(e)

// scratch (static device globals — no allocation)
__device__ float g_h[BB * NN * DM];    // h[b][n][d] = tanh(x@Wx+bx)
__device__ float g_p[BB * NN * DM];    // P row-major: exp2(c*(u+bp))
__device__ float g_qt[BB * DM * NN];   // Q transposed: exp2(-c*u)[b][d][n]

__device__ __forceinline__ float ex2_fast(float x) {
    float y; asm("ex2.approx.f32 %0, %1;" : "=f"(y) : "f"(x)); return y;
}
__device__ __forceinline__ float rcp_fast(float x) {
    float y; asm("rcp.approx.f32 %0, %1;" : "=f"(y) : "f"(x)); return y;
}

// ---------------------------------------------------------------------------
// Kernel A (R6 split-K version — best measured): h = tanh(x @ Wx + bx);
// P (row-major) / Q (transposed). 4 rows/block, K split across thread-halves.
// grid = 256 blocks, 512 threads.
// ---------------------------------------------------------------------------
__global__ __launch_bounds__(512) void kA(const float* __restrict__ x,
                                          const float* __restrict__ pos,
                                          const float* __restrict__ Wx,
                                          const float* __restrict__ bx,
                                          const float* __restrict__ Wp,
                                          const float* __restrict__ bp) {
    __shared__ float s_x[DIN][4];    // 8KB, x tile transposed
    __shared__ float s_part[4][DM];  // 4KB, partial sums from upper K-half
    const int t = threadIdx.x;
    const int row0 = blockIdx.x * 4;
    const int c  = t & (DM - 1);
    const int kh = t >> 8;

    for (int e = t; e < DIN * 4; e += 512) {
        int r = e >> 9, cc = e & (DIN - 1);
        s_x[cc][r] = x[(row0 + r) * DIN + cc];
    }
    __syncthreads();

    float a0 = 0.f, a1 = 0.f, a2 = 0.f, a3 = 0.f;
    const int kb = kh << 8;
#pragma unroll 8
    for (int k = 0; k < 256; k++) {
        float wv = Wx[(kb + k) * DM + c];
        float4 xv = *(const float4*)&s_x[kb + k][0];
        a0 += xv.x * wv; a1 += xv.y * wv;
        a2 += xv.z * wv; a3 += xv.w * wv;
    }
    if (kh) {
        s_part[0][c] = a0; s_part[1][c] = a1;
        s_part[2][c] = a2; s_part[3][c] = a3;
    }
    __syncthreads();
    if (!kh) {
        const float bias = bx[c];
        a0 += s_part[0][c] + bias;
        a1 += s_part[1][c] + bias;
        a2 += s_part[2][c] + bias;
        a3 += s_part[3][c] + bias;
        g_h[(row0 + 0) * DM + c] = tanhf(a0);
        g_h[(row0 + 1) * DM + c] = tanhf(a1);
        g_h[(row0 + 2) * DM + c] = tanhf(a2);
        g_h[(row0 + 3) * DM + c] = tanhf(a3);

        const int b = row0 / NN;
        const int n0 = row0 % NN;
        const float w0 = Wp[0 * DM + c], w1 = Wp[1 * DM + c];
        const float w2 = Wp[2 * DM + c], w3 = Wp[3 * DM + c];
        const float bpv = bp[c];
#pragma unroll
        for (int r = 0; r < 4; r++) {
            const float* p = pos + (row0 + r) * 4;
            float u = p[0] * w0 + p[1] * w1 + p[2] * w2 + p[3] * w3;
            g_p[(row0 + r) * DM + c] = ex2_fast(C2LOG2E * (u + bpv));
            g_qt[(b * DM + c) * NN + n0 + r] = ex2_fast(-C2LOG2E * u);
        }
    }
}

// ---------------------------------------------------------------------------
// Kernel Score (R4 skeleton, i-tile 4): Block = 4 query rows x 256 j's.
// grid = (B*N/4)*2 = 512 blocks, 256 threads. Thread owns one j.
// score_ij = W - 2*sum_d w_d / (1 + P_i[d]*Q_j[d]);  2 RCPs per d (1 per 2 rows)
// ---------------------------------------------------------------------------
__global__ __launch_bounds__(256) void kScore(const float* __restrict__ w,
                                              float* __restrict__ attn_out) {
    __shared__ float s_pi[DM][4];   // P rows i0..i0+3 : 4KB
    __shared__ float s_wn[DM];      // -2*w : 1KB
    __shared__ float s_W;

    const int t = threadIdx.x;
    const int jt = blockIdx.x & 1;            // j-tile
    const int it = blockIdx.x >> 1;           // row-quad index [0, B*N/4)
    const int b  = it / (NN / 4);
    const int i0 = (it % (NN / 4)) * 4;
    const int j  = jt * 256 + t;

    if (t < DM) s_wn[t] = -2.0f * w[t];
    if (t < 32) {
        float s = 0.f;
#pragma unroll
        for (int k = 0; k < 8; k++) s += w[t + 32 * k];
#pragma unroll
        for (int o = 16; o; o >>= 1) s += __shfl_xor_sync(0xffffffffu, s, o);
        if (t == 0) s_W = s;
    }
    {
        const float* prow = g_p + (b * NN + i0) * DM;
        for (int e = t; e < 4 * DM; e += 256) {
            int r = e >> 8, d = e & (DM - 1);
            s_pi[d][r] = prow[r * DM + d];     // coalesced within each row
        }
    }
    __syncthreads();
    const float W = s_W;

    float acc0 = 0.f, acc1 = 0.f, acc2 = 0.f, acc3 = 0.f;
    const float* qp = g_qt + b * DM * NN + j;
    float qbuf[4];
#pragma unroll
    for (int p = 0; p < 4; p++) qbuf[p] = qp[p * NN];

    for (int d0 = 0; d0 < DM; d0 += 4) {
        float qc[4];
#pragma unroll
        for (int p = 0; p < 4; p++) qc[p] = qbuf[p];
        if (d0 + 4 < DM) {
#pragma unroll
            for (int p = 0; p < 4; p++) qbuf[p] = qp[(d0 + 4 + p) * NN];
        }
#pragma unroll
        for (int dd = 0; dd < 4; dd++) {
            const int d = d0 + dd;
            const float wn = s_wn[d];
            const float4 pi = *(const float4*)&s_pi[d][0];  // broadcast LDS.128
            const float qj = qc[dd];
            float de0 = fmaf(pi.x, qj, 1.0f);
            float de1 = fmaf(pi.y, qj, 1.0f);
            float de2 = fmaf(pi.z, qj, 1.0f);
            float de3 = fmaf(pi.w, qj, 1.0f);
            float r01 = rcp_fast(de0 * de1);
            float r23 = rcp_fast(de2 * de3);
            float w01 = wn * r01;
            float w23 = wn * r23;
            acc0 += w01 * de1;
            acc1 += w01 * de0;
            acc2 += w23 * de3;
            acc3 += w23 * de2;
        }
    }
    float* arow = attn_out + (b * NN + i0) * NN + j;
    arow[0 * NN] = W + acc0;
    arow[1 * NN] = W + acc1;
    arow[2 * NN] = W + acc2;
    arow[3 * NN] = W + acc3;
}

// ---------------------------------------------------------------------------
// Kernel SoftOut (R4 exact): masked softmax over 4 rows + output GEMM.
// grid = B*N/4 = 256 blocks, 512 threads.
// ---------------------------------------------------------------------------
__global__ __launch_bounds__(512) void kSoftOut(const int* __restrict__ mask,
                                                float* __restrict__ out,
                                                float* __restrict__ attn_out) {
    __shared__ float s_attn[4][NN];   // scores -> probs, 8KB

    const int t = threadIdx.x;
    const int blk = blockIdx.x;
    const int b = blk / (NN / 4);
    const int i0 = (blk % (NN / 4)) * 4;

    {
        const float4* src = (const float4*)(attn_out + (b * NN + i0) * NN);
        float4* dst = (float4*)&s_attn[0][0];
        for (int e = t; e < 4 * NN / 4; e += 512) dst[e] = src[e];
    }
    __syncthreads();

    const int wid = t >> 5, lane = t & 31;
    if (wid < 4) {
        const int i = i0 + wid;
        const int4* m4 = (const int4*)(mask + (b * NN + i) * NN);
        float4* s4 = (float4*)&s_attn[wid][0];
        int4 mv[4];
        float4 sv[4];
#pragma unroll
        for (int k = 0; k < 4; k++) {
            mv[k] = m4[lane + 32 * k];
            sv[k] = s4[lane + 32 * k];
        }
        float mx = -INFINITY;
#pragma unroll
        for (int k = 0; k < 4; k++) {
            if (mv[k].x) mx = fmaxf(mx, sv[k].x);
            if (mv[k].y) mx = fmaxf(mx, sv[k].y);
            if (mv[k].z) mx = fmaxf(mx, sv[k].z);
            if (mv[k].w) mx = fmaxf(mx, sv[k].w);
        }
#pragma unroll
        for (int o = 16; o; o >>= 1) mx = fmaxf(mx, __shfl_xor_sync(0xffffffffu, mx, o));
        float sum = 0.f;
#pragma unroll
        for (int k = 0; k < 4; k++) {
            sv[k].x = mv[k].x ? __expf(sv[k].x - mx) : 0.f;
            sv[k].y = mv[k].y ? __expf(sv[k].y - mx) : 0.f;
            sv[k].z = mv[k].z ? __expf(sv[k].z - mx) : 0.f;
            sv[k].w = mv[k].w ? __expf(sv[k].w - mx) : 0.f;
            sum += sv[k].x + sv[k].y + sv[k].z + sv[k].w;
        }
#pragma unroll
        for (int o = 16; o; o >>= 1) sum += __shfl_xor_sync(0xffffffffu, sum, o);
        const float inv = (sum > 0.f) ? 1.f / sum : 0.f;
        float4* arow4 = (float4*)(attn_out + (b * NN + i) * NN);
#pragma unroll
        for (int k = 0; k < 4; k++) {
            sv[k].x *= inv; sv[k].y *= inv; sv[k].z *= inv; sv[k].w *= inv;
            s4[lane + 32 * k] = sv[k];
            arow4[lane + 32 * k] = sv[k];
        }
    }
    __syncthreads();

    const int d = t & (DM - 1);
    const int half = t >> 8;
    float o0 = 0.f, o1 = 0.f;
    const float* hb = g_h + b * NN * DM + d;
    const float4* pA = (const float4*)&s_attn[2 * half][0];
    const float4* pB = (const float4*)&s_attn[2 * half + 1][0];
#pragma unroll 2
    for (int j4 = 0; j4 < NN / 4; j4++) {
        float4 a = pA[j4];
        float4 c = pB[j4];
        float h0 = hb[(4 * j4 + 0) * DM];
        float h1 = hb[(4 * j4 + 1) * DM];
        float h2 = hb[(4 * j4 + 2) * DM];
        float h3 = hb[(4 * j4 + 3) * DM];
        o0 += a.x * h0 + a.y * h1 + a.z * h2 + a.w * h3;
        o1 += c.x * h0 + c.y * h1 + c.z * h2 + c.w * h3;
    }
    out[(b * NN + i0 + 2 * half + 0) * DM + d] = o0;
    out[(b * NN + i0 + 2 * half + 1) * DM + d] = o1;
}

// ---------------------------------------------------------------------------
extern "C" void kernel_launch(void* const* d_in, const int* in_sizes, int n_in,
                              void* d_out, int out_size) {
    const float* x    = (const float*)d_in[0];  // [2,512,512]
    const float* pos  = (const float*)d_in[1];  // [2,512,4]
    const int*   mask = (const int*)  d_in[2];  // [2,512,512]
    const float* Wx   = (const float*)d_in[3];  // [512,256]
    const float* bx   = (const float*)d_in[4];  // [256]
    const float* Wp   = (const float*)d_in[5];  // [4,256]
    const float* bp   = (const float*)d_in[6];  // [256]
    const float* w    = (const float*)d_in[7];  // [256]

    float* out      = (float*)d_out;            // [2,512,256]
    float* attn_out = out + BB * NN * DM;       // [2,512,512]

    kA<<<BB * NN / 4, 512>>>(x, pos, Wx, bx, Wp, bp);
    kScore<<<(BB * NN / 4) * 2, 256>>>(w, attn_out);
    kSoftOut<<<BB * NN / 4, 512>>>(mask, out, attn_out);
}